// round 5
// baseline (speedup 1.0000x reference)
#include <cuda_runtime.h>

// CRF NLL, exp-domain forward scan. 4 warps (128 threads) per batch,
// 2 threads per "to" tag (each does a 32-wide half dot product).
// q_s[to] = (sum_from q_{s-1}[from] * E[from,to]) * exp(f_s[to]) / q_{s-1}[0]
// C_s = C_{s-1} + log(q_{s-1}[0]);  part_s = log(q_s) + C_s.

constexpr int Bb = 512;
constexpr int Ss = 512;
constexpr int Tt = 64;
constexpr int START = Tt - 2;
constexpr int STOP  = Tt - 1;
constexpr int PD    = 4;          // feats prefetch depth (steps)
constexpr int NT    = 128;        // threads per block
constexpr int HPAD  = 36;         // float offset of FROM-half 1 in a q row (32 + 4 pad)
constexpr int QROW  = 72;         // padded q row (floats), 16B-aligned

__device__ float g_partial[Bb];
__device__ unsigned int g_count = 0;

typedef unsigned long long u64;

static __device__ __forceinline__ u64 fma2(u64 a, u64 b, u64 c) {
    u64 d;
    asm("fma.rn.f32x2 %0, %1, %2, %3;" : "=l"(d) : "l"(a), "l"(b), "l"(c));
    return d;
}
static __device__ __forceinline__ u64 add2(u64 a, u64 b) {
    u64 d;
    asm("add.rn.f32x2 %0, %1, %2;" : "=l"(d) : "l"(a), "l"(b));
    return d;
}
static __device__ __forceinline__ u64 pack2(float lo, float hi) {
    u64 d;
    asm("mov.b64 %0, {%1, %2};" : "=l"(d) : "f"(lo), "f"(hi));
    return d;
}
static __device__ __forceinline__ void unpack2(u64 v, float& lo, float& hi) {
    asm("mov.b64 {%0, %1}, %2;" : "=f"(lo), "=f"(hi) : "l"(v));
}
static __device__ __forceinline__ float rcp_approx(float x) {
    float r;
    asm("rcp.approx.f32 %0, %1;" : "=f"(r) : "f"(x));
    return r;
}

__global__ __launch_bounds__(NT) void crf_kernel(
    const float* __restrict__ feats,
    const unsigned char* __restrict__ mask8,
    const int* __restrict__ tags,
    const float* __restrict__ trans,
    float* __restrict__ out)
{
    const int b   = blockIdx.x;
    const int tid = threadIdx.x;          // 0..127
    const int tag = tid >> 1;             // 0..63 (adjacent lanes share a tag)
    const int h   = tid & 1;              // FROM-half: 0 -> from 0..31, 1 -> from 32..63

    __shared__ __align__(16) float qbuf[2][QROW];  // q (exp domain), halves padded apart
    __shared__ float red[NT];
    __shared__ int   ired[NT];
    __shared__ int   shL;
    __shared__ bool  is_last;

    // position of tag within the padded q row
    const int qpos = (tag >> 5) * HPAD + (tag & 31);

    // ---- mask layout probe (uint8 vs int32) + sequence length ----
    const int* mask32 = reinterpret_cast<const int*>(mask8);
    const bool is32 = (mask8[0] == 1 && mask8[1] == 0 && mask8[2] == 0 && mask8[3] == 0);

    int cnt = 0;
    #pragma unroll
    for (int k = 0; k < Ss / NT; ++k) {
        int s  = tid + k * NT;
        int mv = is32 ? mask32[b * Ss + s] : (int)mask8[b * Ss + s];
        cnt += (mv != 0);
    }
    ired[tid] = cnt;
    __syncthreads();
    if (tid == 0) {
        int L = 0;
        #pragma unroll
        for (int i = 0; i < NT; ++i) L += ired[i];
        shL = L;
    }
    __syncthreads();
    const int L = shL;                   // >= S/2 = 256

    const float* fb = feats + (size_t)b * Ss * Tt;
    const int*   tg = tags + b * Ss;

    // ---- gold path score ----
    float gsum = 0.f;
    for (int s = tid; s < L; s += NT) {
        int t1 = tg[s];
        int t0 = (s == 0) ? START : tg[s - 1];
        gsum += fb[s * Tt + t1] + trans[t0 * Tt + t1];
    }
    red[tid] = gsum;
    __syncthreads();
    float gold = 0.f;                    // valid in tid 0 only
    if (tid == 0) {
        #pragma unroll
        for (int i = 0; i < NT; ++i) gold += red[i];
        gold += trans[tg[L - 1] * Tt + STOP];
    }

    // ---- E pairs for this thread's 32 FROM values into its tag ----
    u64 E2[16];
    #pragma unroll
    for (int k = 0; k < 16; ++k) {
        int fr = h * 32 + 2 * k;
        E2[k] = pack2(__expf(trans[fr * Tt + tag]),
                      __expf(trans[(fr + 1) * Tt + tag]));
    }

    // ---- init: part_0 = f_0 + trans[START,:]; q_0 = exp(part_0 - part_0[0]) ----
    const float c0 = fb[0] + trans[START * Tt];   // broadcast loads
    float logC = c0;
    if (h == 0) {
        qbuf[0][qpos] = __expf(fb[tag] + trans[START * Tt + tag] - c0);
    }

    // ---- feats pipeline: exp(f) computed at prefetch time (off critical path) ----
    float ef[PD];
    #pragma unroll
    for (int r = 0; r < PD; ++r)
        ef[r] = __expf(fb[(1 + r) * Tt + tag]);   // steps 1..PD (L >= 256)

    float cur = 0.f;

    auto step = [&](int s, float e) {
        __syncthreads();
        const u64* qp = reinterpret_cast<const u64*>(&qbuf[(s - 1) & 1][h * HPAD]);

        const float q0 = qbuf[(s - 1) & 1][0];
        const float r  = rcp_approx(q0);    // overlaps FMA block
        logC += __logf(q0);                 // independent side chain

        u64 a0, a1, a2, a3;
        {
            ulonglong2 w = reinterpret_cast<const ulonglong2*>(qp)[0];
            a0 = fma2(w.x, E2[0], 0ull);
            a1 = fma2(w.y, E2[1], 0ull);
        }
        {
            ulonglong2 w = reinterpret_cast<const ulonglong2*>(qp)[1];
            a2 = fma2(w.x, E2[2], 0ull);
            a3 = fma2(w.y, E2[3], 0ull);
        }
        #pragma unroll
        for (int j = 2; j < 8; ++j) {
            ulonglong2 w = reinterpret_cast<const ulonglong2*>(qp)[j];
            if (j & 1) { a2 = fma2(w.x, E2[2 * j], a2); a3 = fma2(w.y, E2[2 * j + 1], a3); }
            else       { a0 = fma2(w.x, E2[2 * j], a0); a1 = fma2(w.y, E2[2 * j + 1], a1); }
        }
        float lo, hi;
        unpack2(add2(add2(a0, a2), add2(a1, a3)), lo, hi);
        float part = lo + hi;
        part += __shfl_xor_sync(0xffffffffu, part, 1);   // combine the two halves
        cur = part * (e * r);
        if (h == 0) qbuf[s & 1][qpos] = cur;
    };

    // ---- forward scan, unrolled x PD with deep prefetch ----
    int s = 1;
    for (; s + (PD - 1) < L; ) {
        #pragma unroll
        for (int r = 0; r < PD; ++r) {
            const float e = ef[r];
            if (s + PD < L) ef[r] = __expf(fb[(s + PD) * Tt + tag]);
            step(s, e);
            ++s;
        }
    }
    for (; s < L; ++s) {
        step(s, ef[(s - 1) & (PD - 1)]);
    }

    // ---- final transition to STOP ----
    if (h == 0) red[tag] = cur * __expf(trans[tag * Tt + STOP]);
    __syncthreads();
    if (tid == 0) {
        float tot = 0.f;
        #pragma unroll
        for (int i = 0; i < Tt; ++i) tot += red[i];
        const float fwd = logC + __logf(tot);
        g_partial[b] = fwd - gold;
        __threadfence();
        unsigned int c = atomicAdd(&g_count, 1u);
        is_last = (c == (unsigned)gridDim.x - 1);
    }
    __syncthreads();

    // ---- last block: deterministic fixed-order reduction over batches ----
    if (is_last) {
        __threadfence();
        float sum = 0.f;
        #pragma unroll
        for (int k = 0; k < Bb / NT; ++k) {
            float v;
            asm volatile("ld.global.cg.f32 %0, [%1];" : "=f"(v)
                         : "l"(&g_partial[tid + k * NT]));
            sum += v;
        }
        red[tid] = sum;
        __syncthreads();
        if (tid == 0) {
            float tot = 0.f;
            #pragma unroll
            for (int i = 0; i < NT; ++i) tot += red[i];
            out[0] = tot;
            g_count = 0;   // reset for next (graph-replayed) launch
        }
    }
}

extern "C" void kernel_launch(void* const* d_in, const int* in_sizes, int n_in,
                              void* d_out, int out_size)
{
    (void)in_sizes; (void)n_in; (void)out_size;
    const float*         feats = (const float*)d_in[0];
    const unsigned char* mask  = (const unsigned char*)d_in[1];
    const int*           tags  = (const int*)d_in[2];
    const float*         trans = (const float*)d_in[3];

    crf_kernel<<<Bb, NT>>>(feats, mask, tags, trans, (float*)d_out);
}